// round 11
// baseline (speedup 1.0000x reference)
#include <cuda_runtime.h>
#include <cuda_bf16.h>
#include <cuda_fp16.h>
#include <cstdint>

// Problem shape (fixed by reference)
#define BB 4
#define HH 16
#define SS 2048
#define DD 64
#define TQ 32            // queries per CTA
#define KC 128           // keys per chunk
#define NCHUNK (SS/KC)   // 16
#define NT 512
#define SCALE 0.125f

#define EPW 1028         // e-plane row stride, 32-bit words (1028 % 32 == 4)
#define KPS 136          // K plane row stride, words (136 % 32 == 8), rows = d2 (32)
#define VPS 68           // V plane row stride, words (68 % 32 == 4),  rows = d (64)

#define OUT_ELEMS (BB*HH*SS*DD)

#define W_EP (TQ*EPW)    // 32896
#define W_PL 4352        // max(32*136, 64*68)
#define SMEM_WORDS (W_EP + 2*W_PL + TQ*DD + TQ*16 + TQ)
#define SMEM_BYTES (SMEM_WORDS * 4)   // ~176.8 KB

// D(16x8 f32) += A(16x16 bf16, row) * B(16x8 bf16, col)
#define MMA16(d, a0, a1, a2, a3, b0, b1)                                       \
    asm volatile(                                                              \
        "mma.sync.aligned.m16n8k16.row.col.f32.bf16.bf16.f32 "                 \
        "{%0,%1,%2,%3},{%4,%5,%6,%7},{%8,%9},{%0,%1,%2,%3};"                   \
        : "+f"(d[0]), "+f"(d[1]), "+f"(d[2]), "+f"(d[3])                       \
        : "r"(a0), "r"(a1), "r"(a2), "r"(a3), "r"(b0), "r"(b1))

// D(16x8 f32) += A(16x16 f16, row) * B(16x8 f16, col)
#define MMAH(d, a0, a1, a2, a3, b0, b1)                                        \
    asm volatile(                                                              \
        "mma.sync.aligned.m16n8k16.row.col.f32.f16.f16.f32 "                   \
        "{%0,%1,%2,%3},{%4,%5,%6,%7},{%8,%9},{%0,%1,%2,%3};"                   \
        : "+f"(d[0]), "+f"(d[1]), "+f"(d[2]), "+f"(d[3])                       \
        : "r"(a0), "r"(a1), "r"(a2), "r"(a3), "r"(b0), "r"(b1))

// split (x,y) into packed bf16x2 hi and lo planes
__device__ __forceinline__ void bsplit2(float x, float y, uint32_t& hi, uint32_t& lo) {
    __nv_bfloat162 H = __floats2bfloat162_rn(x, y);
    float2 hf = __bfloat1622float2(H);
    __nv_bfloat162 L = __floats2bfloat162_rn(x - hf.x, y - hf.y);
    hi = *reinterpret_cast<uint32_t*>(&H);
    lo = *reinterpret_cast<uint32_t*>(&L);
}

// split (x,y) into packed f16x2 hi and lo planes
__device__ __forceinline__ void hsplit2(float x, float y, uint32_t& hi, uint32_t& lo) {
    __half2 H = __floats2half2_rn(x, y);
    float2 hf = __half22float2(H);
    __half2 L = __floats2half2_rn(x - hf.x, y - hf.y);
    hi = *reinterpret_cast<uint32_t*>(&H);
    lo = *reinterpret_cast<uint32_t*>(&L);
}

__device__ __forceinline__ uint32_t packh2(float x, float y) {
    __half2 v = __floats2half2_rn(x, y);
    return *reinterpret_cast<uint32_t*>(&v);
}

__global__ __launch_bounds__(NT, 1)
void sdpa_v2(const float* __restrict__ Q, const float* __restrict__ K,
             const float* __restrict__ V, const int* __restrict__ mask,
             float* __restrict__ out, float* __restrict__ wts) {
    extern __shared__ uint32_t sm[];
    uint32_t* EP = sm;               // e-plane: 32 rows x 1028 words (fp16 pairs)
    uint32_t* PH = sm + W_EP;        // K/V hi plane
    uint32_t* PL = PH + W_PL;        // K/V lo plane
    float* Qs   = (float*)(PL + W_PL);   // 32 x 64 raw Q
    float* part = Qs + TQ * DD;          // [32][16]
    float* invs = part + TQ * 16;        // [32]

    const int h  = blockIdx.x;
    const int q0 = blockIdx.y * TQ;
    const int b  = blockIdx.z;

    const int tid = threadIdx.x;
    const int w   = tid >> 5;   // warp 0..15
    const int l   = tid & 31;
    const int g   = l >> 2;     // 0..7
    const int tg  = l & 3;      // 0..3

    const size_t bh = (size_t)(b * HH + h);
    const float* Qb = Q + bh * SS * DD + (size_t)q0 * DD;
    const float* Kb = K + bh * SS * DD;
    const float* Vb = V + bh * SS * DD;
    const int*   Mb = mask + (size_t)b * SS * SS + (size_t)q0 * SS;
    float* Ob = out + bh * SS * DD + (size_t)q0 * DD;
    float* Wb = wts + bh * SS * SS + (size_t)q0 * SS;

    ((float4*)Qs)[tid] = ((const float4*)Qb)[tid];   // 512 float4 = 2048 floats
    __syncthreads();

    // Q fragments for both m-tiles (rows 16*mt + {g, g+8}), bf16 hi/lo, SCALE folded
    uint32_t Qh[2][4][4], Ql[2][4][4];
#pragma unroll
    for (int mt = 0; mt < 2; mt++) {
        const int r0 = 16 * mt + g, r1 = r0 + 8;
#pragma unroll
        for (int dk = 0; dk < 4; dk++) {
            const int base = 16 * dk + 2 * tg;
            float2 p00 = *(const float2*)&Qs[r0 * DD + base];
            float2 p10 = *(const float2*)&Qs[r1 * DD + base];
            float2 p01 = *(const float2*)&Qs[r0 * DD + base + 8];
            float2 p11 = *(const float2*)&Qs[r1 * DD + base + 8];
            bsplit2(p00.x * SCALE, p00.y * SCALE, Qh[mt][dk][0], Ql[mt][dk][0]);
            bsplit2(p10.x * SCALE, p10.y * SCALE, Qh[mt][dk][1], Ql[mt][dk][1]);
            bsplit2(p01.x * SCALE, p01.y * SCALE, Qh[mt][dk][2], Ql[mt][dk][2]);
            bsplit2(p11.x * SCALE, p11.y * SCALE, Qh[mt][dk][3], Ql[mt][dk][3]);
        }
    }

    float s0 = 0.f, s1 = 0.f, s2 = 0.f, s3 = 0.f;  // rows g, g+8, g+16, g+24

    // ================= Phase 1: e = exp(masked QK^T) -> fp16 e-plane =======
    for (int c = 0; c < NCHUNK; c++) {
        const int cbase = c * KC;
        __syncthreads();
        // stage K chunk: warp w owns keys 8w..8w+7; lane = d2 (coalesced rows)
#pragma unroll
        for (int j = 0; j < 8; j++) {
            const int key = 8 * w + j;
            float2 kv = *(const float2*)&Kb[(size_t)(cbase + key) * DD + 2 * l];
            uint32_t hi, lo;
            bsplit2(kv.x, kv.y, hi, lo);
            const int wi = l * KPS + (key ^ ((l >> 2) & 7));
            PH[wi] = hi;
            PL[wi] = lo;
        }
        __syncthreads();

        // mask for this warp's 8 keys, 4 row-groups (in flight during MMAs)
        const int mc = cbase + 8 * w + 2 * tg;
        int2 m00 = *(const int2*)&Mb[(size_t)g * SS + mc];
        int2 m01 = *(const int2*)&Mb[(size_t)(g + 8) * SS + mc];
        int2 m10 = *(const int2*)&Mb[(size_t)(g + 16) * SS + mc];
        int2 m11 = *(const int2*)&Mb[(size_t)(g + 24) * SS + mc];

        float acc0[4] = {0.f, 0.f, 0.f, 0.f};
        float acc1[4] = {0.f, 0.f, 0.f, 0.f};
        const int key = 8 * w + g;
#pragma unroll
        for (int dk = 0; dk < 4; dk++) {
            const int d2a = 8 * dk + tg, d2b = d2a + 4;
            const int sa = (d2a >> 2) & 7, sb = (d2b >> 2) & 7;
            const int ia = d2a * KPS + (key ^ sa);
            const int ib = d2b * KPS + (key ^ sb);
            uint32_t bh0 = PH[ia], bh1 = PH[ib];
            uint32_t bl0 = PL[ia], bl1 = PL[ib];
            MMA16(acc0, Qh[0][dk][0], Qh[0][dk][1], Qh[0][dk][2], Qh[0][dk][3], bh0, bh1);
            MMA16(acc0, Qh[0][dk][0], Qh[0][dk][1], Qh[0][dk][2], Qh[0][dk][3], bl0, bl1);
            MMA16(acc0, Ql[0][dk][0], Ql[0][dk][1], Ql[0][dk][2], Ql[0][dk][3], bh0, bh1);
            MMA16(acc1, Qh[1][dk][0], Qh[1][dk][1], Qh[1][dk][2], Qh[1][dk][3], bh0, bh1);
            MMA16(acc1, Qh[1][dk][0], Qh[1][dk][1], Qh[1][dk][2], Qh[1][dk][3], bl0, bl1);
            MMA16(acc1, Ql[1][dk][0], Ql[1][dk][1], Ql[1][dk][2], Ql[1][dk][3], bh0, bh1);
        }

        // epilogue: mask -> exp -> fp16 pairs to e-plane, sums in regs
        {
            const int wc = c * 64 + 4 * w + tg;
            float e0 = m00.x ? __expf(acc0[0]) : 0.f;
            float e1 = m00.y ? __expf(acc0[1]) : 0.f;
            float e2 = m01.x ? __expf(acc0[2]) : 0.f;
            float e3 = m01.y ? __expf(acc0[3]) : 0.f;
            EP[g * EPW + wc]        = packh2(e0, e1);
            EP[(g + 8) * EPW + wc]  = packh2(e2, e3);
            s0 += e0 + e1; s1 += e2 + e3;
            e0 = m10.x ? __expf(acc1[0]) : 0.f;
            e1 = m10.y ? __expf(acc1[1]) : 0.f;
            e2 = m11.x ? __expf(acc1[2]) : 0.f;
            e3 = m11.y ? __expf(acc1[3]) : 0.f;
            EP[(g + 16) * EPW + wc] = packh2(e0, e1);
            EP[(g + 24) * EPW + wc] = packh2(e2, e3);
            s2 += e0 + e1; s3 += e2 + e3;
        }
    }

    // ================= row-sum reduction -> invs[32] =======================
    s0 += __shfl_xor_sync(0xffffffffu, s0, 1);
    s0 += __shfl_xor_sync(0xffffffffu, s0, 2);
    s1 += __shfl_xor_sync(0xffffffffu, s1, 1);
    s1 += __shfl_xor_sync(0xffffffffu, s1, 2);
    s2 += __shfl_xor_sync(0xffffffffu, s2, 1);
    s2 += __shfl_xor_sync(0xffffffffu, s2, 2);
    s3 += __shfl_xor_sync(0xffffffffu, s3, 1);
    s3 += __shfl_xor_sync(0xffffffffu, s3, 2);
    if (tg == 0) {
        part[g * 16 + w]        = s0;
        part[(g + 8) * 16 + w]  = s1;
        part[(g + 16) * 16 + w] = s2;
        part[(g + 24) * 16 + w] = s3;
    }
    __syncthreads();
    if (tid < TQ) {
        float t = 0.f;
#pragma unroll
        for (int j = 0; j < 16; j++) t += part[tid * 16 + j];
        invs[tid] = 1.0f / t;
    }
    __syncthreads();

    // ================= Phase 2: normalized weights to global ===============
#pragma unroll
    for (int rr = 0; rr < 2; rr++) {
        const int r = 2 * w + rr;
        const float inv = invs[r];
#pragma unroll
        for (int j = 0; j < 8; j++) {
            uint4 u = *(const uint4*)&EP[r * EPW + 4 * (l + 32 * j)];
            float2 f0 = __half22float2(*reinterpret_cast<__half2*>(&u.x));
            float2 f1 = __half22float2(*reinterpret_cast<__half2*>(&u.y));
            float2 f2 = __half22float2(*reinterpret_cast<__half2*>(&u.z));
            float2 f3 = __half22float2(*reinterpret_cast<__half2*>(&u.w));
            float* dst = &Wb[(size_t)r * SS + 8 * (l + 32 * j)];
            *(float4*)dst       = make_float4(f0.x * inv, f0.y * inv, f1.x * inv, f1.y * inv);
            *(float4*)(dst + 4) = make_float4(f2.x * inv, f2.y * inv, f3.x * inv, f3.y * inv);
        }
    }

    // ================= Phase 3: O^T = V^T @ P^T (f16, 2-term) ==============
    const int dt = w & 3, nt = w >> 2;
    float oacc[4] = {0.f, 0.f, 0.f, 0.f};
    for (int c = 0; c < NCHUNK; c++) {
        const int cbase = c * KC;
        __syncthreads();   // planes free of previous readers
        // stage V chunk: warp w owns k2 = 4w..4w+3 (key pairs); lane = d
#pragma unroll
        for (int j = 0; j < 4; j++) {
            const int k2 = 4 * w + j;
#pragma unroll
            for (int p = 0; p < 2; p++) {
                const int d = l + 32 * p;
                float va = Vb[(size_t)(cbase + 2 * k2) * DD + d];
                float vb2 = Vb[(size_t)(cbase + 2 * k2 + 1) * DD + d];
                uint32_t hi, lo;
                hsplit2(va, vb2, hi, lo);
                const int wi = d * VPS + (k2 ^ ((d >> 3) & 3));
                PH[wi] = hi;
                PL[wi] = lo;
            }
        }
        __syncthreads();
#pragma unroll
        for (int s = 0; s < 8; s++) {
            const int da = 16 * dt + g, db = da + 8;
            const int ca = 8 * s + tg, cb = ca + 4;
            const int sa2 = (da >> 3) & 3, sb2 = (db >> 3) & 3;
            const int i0 = da * VPS + (ca ^ sa2), i1 = db * VPS + (ca ^ sb2);
            const int i2 = da * VPS + (cb ^ sa2), i3 = db * VPS + (cb ^ sb2);
            uint32_t ah0 = PH[i0], ah1 = PH[i1], ah2 = PH[i2], ah3 = PH[i3];
            uint32_t al0 = PL[i0], al1 = PL[i1], al2 = PL[i2], al3 = PL[i3];
            const int bw = (8 * nt + g) * EPW + c * 64 + 8 * s + tg;
            uint32_t b0 = EP[bw], b1 = EP[bw + 4];   // e used directly as f16 B
            MMAH(oacc, ah0, ah1, ah2, ah3, b0, b1);
            MMAH(oacc, al0, al1, al2, al3, b0, b1);
        }
    }

    // write O (normalize with row inverses)
    const int row0 = 8 * nt + 2 * tg, row1 = row0 + 1;
    const int d0 = 16 * dt + g, d1 = d0 + 8;
    const float i0v = invs[row0], i1v = invs[row1];
    Ob[(size_t)row0 * DD + d0] = oacc[0] * i0v;
    Ob[(size_t)row1 * DD + d0] = oacc[1] * i1v;
    Ob[(size_t)row0 * DD + d1] = oacc[2] * i0v;
    Ob[(size_t)row1 * DD + d1] = oacc[3] * i1v;
}

extern "C" void kernel_launch(void* const* d_in, const int* in_sizes, int n_in,
                              void* d_out, int out_size) {
    (void)in_sizes; (void)n_in; (void)out_size;
    const float* Q    = (const float*)d_in[0];
    const float* K    = (const float*)d_in[1];
    const float* V    = (const float*)d_in[2];
    const int*   mask = (const int*)d_in[3];
    float* out = (float*)d_out;
    float* wts = out + OUT_ELEMS;

    static int smem_set = 0;
    if (!smem_set) {
        cudaFuncSetAttribute(sdpa_v2,
                             cudaFuncAttributeMaxDynamicSharedMemorySize,
                             SMEM_BYTES);
        smem_set = 1;
    }

    dim3 grid(HH, SS / TQ, BB);  // h fastest -> mask tile reused across heads in L2
    sdpa_v2<<<grid, NT, SMEM_BYTES>>>(Q, K, V, mask, out, wts);
}

// round 12
// speedup vs baseline: 1.0531x; 1.0531x over previous
#include <cuda_runtime.h>
#include <cuda_bf16.h>
#include <cuda_fp16.h>
#include <cstdint>

// Problem shape (fixed by reference)
#define BB 4
#define HH 16
#define SS 2048
#define DD 64
#define TQ 16            // queries per CTA
#define KC 128           // keys per chunk
#define NCHUNK (SS/KC)   // 16
#define NT 256
#define SCALE 0.125f

#define EPW 1028         // e-plane row stride, 32-bit words (1028 % 32 == 4)
#define KPS 136          // K plane row stride, words (136 % 32 == 8), rows = d2 (32)
#define VPS 68           // V plane row stride, words (68 % 32 == 4),  rows = d (64)

#define OUT_ELEMS (BB*HH*SS*DD)

#define W_EP 16448       // 16 * 1028
#define W_PL 4352        // max(32*136, 64*68) = 4352
#define SMEM_WORDS (W_EP + 2*W_PL + TQ*DD + 128 + 16)
#define SMEM_BYTES (SMEM_WORDS * 4)

// D(16x8 f32) += A(16x16 bf16, row) * B(16x8 bf16, col)
#define MMA16(d, a0, a1, a2, a3, b0, b1)                                       \
    asm volatile(                                                              \
        "mma.sync.aligned.m16n8k16.row.col.f32.bf16.bf16.f32 "                 \
        "{%0,%1,%2,%3},{%4,%5,%6,%7},{%8,%9},{%0,%1,%2,%3};"                   \
        : "+f"(d[0]), "+f"(d[1]), "+f"(d[2]), "+f"(d[3])                       \
        : "r"(a0), "r"(a1), "r"(a2), "r"(a3), "r"(b0), "r"(b1))

// D(16x8 f32) += A(16x16 f16, row) * B(16x8 f16, col)
#define MMAH(d, a0, a1, a2, a3, b0, b1)                                        \
    asm volatile(                                                              \
        "mma.sync.aligned.m16n8k16.row.col.f32.f16.f16.f32 "                   \
        "{%0,%1,%2,%3},{%4,%5,%6,%7},{%8,%9},{%0,%1,%2,%3};"                   \
        : "+f"(d[0]), "+f"(d[1]), "+f"(d[2]), "+f"(d[3])                       \
        : "r"(a0), "r"(a1), "r"(a2), "r"(a3), "r"(b0), "r"(b1))

// split (x,y) into packed bf16x2 hi and lo planes (hi + lo ~ fp32-16bit)
__device__ __forceinline__ void bsplit2(float x, float y, uint32_t& hi, uint32_t& lo) {
    __nv_bfloat162 H = __floats2bfloat162_rn(x, y);
    float2 hf = __bfloat1622float2(H);
    __nv_bfloat162 L = __floats2bfloat162_rn(x - hf.x, y - hf.y);
    hi = *reinterpret_cast<uint32_t*>(&H);
    lo = *reinterpret_cast<uint32_t*>(&L);
}

// split (x,y) into packed f16x2 hi and lo planes
__device__ __forceinline__ void hsplit2(float x, float y, uint32_t& hi, uint32_t& lo) {
    __half2 H = __floats2half2_rn(x, y);
    float2 hf = __half22float2(H);
    __half2 L = __floats2half2_rn(x - hf.x, y - hf.y);
    hi = *reinterpret_cast<uint32_t*>(&H);
    lo = *reinterpret_cast<uint32_t*>(&L);
}

__device__ __forceinline__ uint32_t packh2(float x, float y) {
    __half2 v = __floats2half2_rn(x, y);
    return *reinterpret_cast<uint32_t*>(&v);
}

__global__ __launch_bounds__(NT, 2)
void sdpa_v3(const float* __restrict__ Q, const float* __restrict__ K,
             const float* __restrict__ V, const int* __restrict__ mask,
             float* __restrict__ out, float* __restrict__ wts) {
    extern __shared__ uint32_t sm[];
    uint32_t* EP = sm;               // e-plane: 16 rows x 1028 words (fp16 pairs)
    uint32_t* PH = sm + W_EP;        // K/V hi plane
    uint32_t* PL = PH + W_PL;        // K/V lo plane
    float* Qs   = (float*)(PL + W_PL);   // 16 x 64 raw Q
    float* part = Qs + TQ * DD;          // [16][8]
    float* invs = part + 128;            // [16]

    const int h  = blockIdx.x;
    const int q0 = blockIdx.y * TQ;
    const int b  = blockIdx.z;

    const int tid = threadIdx.x;
    const int w   = tid >> 5;   // warp 0..7
    const int l   = tid & 31;
    const int g   = l >> 2;     // 0..7
    const int tg  = l & 3;      // 0..3

    const size_t bh = (size_t)(b * HH + h);
    const float* Qb = Q + bh * SS * DD + (size_t)q0 * DD;
    const float* Kb = K + bh * SS * DD;
    const float* Vb = V + bh * SS * DD;
    const int*   Mb = mask + (size_t)b * SS * SS + (size_t)q0 * SS;
    float* Ob = out + bh * SS * DD + (size_t)q0 * DD;
    float* Wb = wts + bh * SS * SS + (size_t)q0 * SS;

    ((float4*)Qs)[tid] = ((const float4*)Qb)[tid];
    __syncthreads();

    // Q fragments: bf16 hi/lo split, SCALE folded. a0:(g,k),a1:(g+8,k),a2:(g,k+8),a3:(g+8,k+8)
    uint32_t Qh[4][4], Ql[4][4];
#pragma unroll
    for (int dk = 0; dk < 4; dk++) {
        const int base = 16 * dk + 2 * tg;
        float2 p00 = *(const float2*)&Qs[g * DD + base];
        float2 p10 = *(const float2*)&Qs[(g + 8) * DD + base];
        float2 p01 = *(const float2*)&Qs[g * DD + base + 8];
        float2 p11 = *(const float2*)&Qs[(g + 8) * DD + base + 8];
        bsplit2(p00.x * SCALE, p00.y * SCALE, Qh[dk][0], Ql[dk][0]);
        bsplit2(p10.x * SCALE, p10.y * SCALE, Qh[dk][1], Ql[dk][1]);
        bsplit2(p01.x * SCALE, p01.y * SCALE, Qh[dk][2], Ql[dk][2]);
        bsplit2(p11.x * SCALE, p11.y * SCALE, Qh[dk][3], Ql[dk][3]);
    }

    float s0 = 0.f, s1 = 0.f;   // row-sum partials for rows g, g+8

    // ================= Phase 1: e = exp(masked QK^T) into fp16 e-plane =====
    for (int c = 0; c < NCHUNK; c++) {
        const int cbase = c * KC;
        __syncthreads();
        // stage K chunk: lane = d2 (coalesced 256B rows), XOR-swizzled STS
#pragma unroll
        for (int j = 0; j < 16; j++) {
            const int key = 16 * w + j;
            float2 kv = *(const float2*)&Kb[(size_t)(cbase + key) * DD + 2 * l];
            uint32_t hi, lo;
            bsplit2(kv.x, kv.y, hi, lo);
            const int wi = l * KPS + (key ^ ((l >> 2) & 7));
            PH[wi] = hi;
            PL[wi] = lo;
        }
        __syncthreads();

        // mask for this warp's 16 keys (in flight during MMAs)
        const int mc = cbase + 16 * w + 2 * tg;
        int2 m00 = *(const int2*)&Mb[(size_t)g * SS + mc];
        int2 m01 = *(const int2*)&Mb[(size_t)g * SS + mc + 8];
        int2 m10 = *(const int2*)&Mb[(size_t)(g + 8) * SS + mc];
        int2 m11 = *(const int2*)&Mb[(size_t)(g + 8) * SS + mc + 8];

        float acc0[4] = {0.f, 0.f, 0.f, 0.f};
        float acc1[4] = {0.f, 0.f, 0.f, 0.f};
#pragma unroll
        for (int dk = 0; dk < 4; dk++) {
            const int d2a = 8 * dk + tg, d2b = d2a + 4;
            const int sa = (d2a >> 2) & 7, sb = (d2b >> 2) & 7;
#pragma unroll
            for (int jn = 0; jn < 2; jn++) {
                const int key = 16 * w + 8 * jn + g;
                const int ia = d2a * KPS + (key ^ sa);
                const int ib = d2b * KPS + (key ^ sb);
                uint32_t bh0 = PH[ia], bh1 = PH[ib];
                uint32_t bl0 = PL[ia], bl1 = PL[ib];
                float* A = jn ? acc1 : acc0;
                MMA16(A, Qh[dk][0], Qh[dk][1], Qh[dk][2], Qh[dk][3], bh0, bh1);
                MMA16(A, Qh[dk][0], Qh[dk][1], Qh[dk][2], Qh[dk][3], bl0, bl1);
                MMA16(A, Ql[dk][0], Ql[dk][1], Ql[dk][2], Ql[dk][3], bh0, bh1);
            }
        }
        // epilogue: mask -> exp -> fp16 pairs to e-plane, sums in regs
        {
            const int wc = c * 64 + 8 * w + tg;
            float e0 = m00.x ? __expf(acc0[0]) : 0.f;
            float e1 = m00.y ? __expf(acc0[1]) : 0.f;
            float e2 = m10.x ? __expf(acc0[2]) : 0.f;
            float e3 = m10.y ? __expf(acc0[3]) : 0.f;
            EP[g * EPW + wc]       = packh2(e0, e1);
            EP[(g + 8) * EPW + wc] = packh2(e2, e3);
            s0 += e0 + e1; s1 += e2 + e3;
            e0 = m01.x ? __expf(acc1[0]) : 0.f;
            e1 = m01.y ? __expf(acc1[1]) : 0.f;
            e2 = m11.x ? __expf(acc1[2]) : 0.f;
            e3 = m11.y ? __expf(acc1[3]) : 0.f;
            EP[g * EPW + wc + 4]       = packh2(e0, e1);
            EP[(g + 8) * EPW + wc + 4] = packh2(e2, e3);
            s0 += e0 + e1; s1 += e2 + e3;
        }
    }

    // ================= row-sum reduction -> invs[16] =======================
    s0 += __shfl_xor_sync(0xffffffffu, s0, 1);
    s0 += __shfl_xor_sync(0xffffffffu, s0, 2);
    s1 += __shfl_xor_sync(0xffffffffu, s1, 1);
    s1 += __shfl_xor_sync(0xffffffffu, s1, 2);
    if (tg == 0) {
        part[g * 8 + w]       = s0;
        part[(g + 8) * 8 + w] = s1;
    }
    __syncthreads();
    if (tid < 16) {
        float t = 0.f;
#pragma unroll
        for (int j = 0; j < 8; j++) t += part[tid * 8 + j];
        invs[tid] = 1.0f / t;
    }
    __syncthreads();

    // ================= Phase 2: normalized weights to global ===============
#pragma unroll
    for (int rr = 0; rr < 2; rr++) {
        const int r = 2 * w + rr;
        const float inv = invs[r];
#pragma unroll
        for (int j = 0; j < 8; j++) {
            uint4 u = *(const uint4*)&EP[r * EPW + 4 * (l + 32 * j)];
            float2 f0 = __half22float2(*reinterpret_cast<__half2*>(&u.x));
            float2 f1 = __half22float2(*reinterpret_cast<__half2*>(&u.y));
            float2 f2 = __half22float2(*reinterpret_cast<__half2*>(&u.z));
            float2 f3 = __half22float2(*reinterpret_cast<__half2*>(&u.w));
            float* dst = &Wb[(size_t)r * SS + 8 * (l + 32 * j)];
            *(float4*)dst       = make_float4(f0.x * inv, f0.y * inv, f1.x * inv, f1.y * inv);
            *(float4*)(dst + 4) = make_float4(f2.x * inv, f2.y * inv, f3.x * inv, f3.y * inv);
        }
    }

    // ================= Phase 3: O^T = V^T @ P^T (f16 V split, e direct) ====
    const int dt = w & 3, nt = w >> 2;
    float oacc[4] = {0.f, 0.f, 0.f, 0.f};
    for (int c = 0; c < NCHUNK; c++) {
        const int cbase = c * KC;
        __syncthreads();   // planes free of previous readers
        // stage V chunk: lane = d (coalesced 128B rows), pairs along keys
#pragma unroll
        for (int p = 0; p < 2; p++) {
            const int d = l + 32 * p;
            const int sw = (d >> 3) & 3;
#pragma unroll
            for (int j = 0; j < 8; j++) {
                const int k2 = 8 * w + j;
                float va = Vb[(size_t)(cbase + 2 * k2) * DD + d];
                float vb2 = Vb[(size_t)(cbase + 2 * k2 + 1) * DD + d];
                uint32_t hi, lo;
                hsplit2(va, vb2, hi, lo);
                const int wi = d * VPS + (k2 ^ sw);
                PH[wi] = hi;
                PL[wi] = lo;
            }
        }
        __syncthreads();
#pragma unroll
        for (int s = 0; s < 8; s++) {
            const int da = 16 * dt + g, db = da + 8;
            const int ca = 8 * s + tg, cb = ca + 4;
            const int sa2 = (da >> 3) & 3, sb2 = (db >> 3) & 3;
            const int i0 = da * VPS + (ca ^ sa2), i1 = db * VPS + (ca ^ sb2);
            const int i2 = da * VPS + (cb ^ sa2), i3 = db * VPS + (cb ^ sb2);
            uint32_t ah0 = PH[i0], ah1 = PH[i1], ah2 = PH[i2], ah3 = PH[i3];
            uint32_t al0 = PL[i0], al1 = PL[i1], al2 = PL[i2], al3 = PL[i3];
            const int bw = (8 * nt + g) * EPW + c * 64 + 8 * s + tg;
            uint32_t b0 = EP[bw], b1 = EP[bw + 4];   // e used directly as f16 B
            MMAH(oacc, ah0, ah1, ah2, ah3, b0, b1);
            MMAH(oacc, al0, al1, al2, al3, b0, b1);
        }
    }

    // write O (normalize with row inverses)
    const int row0 = 8 * nt + 2 * tg, row1 = row0 + 1;
    const int d0 = 16 * dt + g, d1 = d0 + 8;
    const float i0v = invs[row0], i1v = invs[row1];
    Ob[(size_t)row0 * DD + d0] = oacc[0] * i0v;
    Ob[(size_t)row1 * DD + d0] = oacc[1] * i1v;
    Ob[(size_t)row0 * DD + d1] = oacc[2] * i0v;
    Ob[(size_t)row1 * DD + d1] = oacc[3] * i1v;
}

extern "C" void kernel_launch(void* const* d_in, const int* in_sizes, int n_in,
                              void* d_out, int out_size) {
    (void)in_sizes; (void)n_in; (void)out_size;
    const float* Q    = (const float*)d_in[0];
    const float* K    = (const float*)d_in[1];
    const float* V    = (const float*)d_in[2];
    const int*   mask = (const int*)d_in[3];
    float* out = (float*)d_out;
    float* wts = out + OUT_ELEMS;

    static int smem_set = 0;
    if (!smem_set) {
        cudaFuncSetAttribute(sdpa_v3,
                             cudaFuncAttributeMaxDynamicSharedMemorySize,
                             SMEM_BYTES);
        smem_set = 1;
    }

    dim3 grid(HH, SS / TQ, BB);  // h fastest -> mask tile reused across heads in L2
    sdpa_v3<<<grid, NT, SMEM_BYTES>>>(Q, K, V, mask, out, wts);
}